// round 14
// baseline (speedup 1.0000x reference)
#include <cuda_runtime.h>
#include <cuda_bf16.h>
#include <cstdint>
#include <cstddef>

#define NB   4
#define NC   64
#define NL   4096
#define NH   128
#define NKE  192          // [hi|x|x] split-bf16 extended K dimension

#define SCALE_LOG2E 14.4269504088896340737f   // 10 * log2(e)
#define THRESH 1e-3f

// ---------------- device scratch (no allocations allowed) ----------------
__device__ __align__(256) __nv_bfloat16 g_Q[NB*NL*NKE];   // [b][l][192] = [qhi|qlo|qhi]
__device__ __align__(256) __nv_bfloat16 g_K[NB*NL*NKE];   // [b][l][192] = [khi|khi|klo]

// ---------------- projection + leakyrelu + projection + l2norm + bf16 split ----------------
#define PJ_POS 32
#define W1_PITCH 68    // [j][c]
#define W2_PITCH 132   // [o][j]
#define XS_PITCH 68    // [p][c]
#define HS_PITCH 132   // [p][j]
#define SA_W1 0
#define SA_W2 (NH*W1_PITCH)                  // 8704
#define SA_XS (SA_W2 + NC*W2_PITCH)          // 17152
#define SA_HS (SA_XS + PJ_POS*XS_PITCH)      // 19328
#define SA_FLOATS (SA_HS + PJ_POS*HS_PITCH)  // 23552
#define SA_BYTES (SA_FLOATS*4)

__global__ void __launch_bounds__(256,2) proj_kernel(const float* __restrict__ xq,
                                                     const float* __restrict__ xk,
                                                     const float* __restrict__ W1,
                                                     const float* __restrict__ W2){
  extern __shared__ float sm_f[];
  float* sm = sm_f;
  const int tid = threadIdx.x;
  const int bpt = NL / PJ_POS;                 // 128 blocks per (tensor,batch)
  const int tb  = blockIdx.x / bpt;            // 0..7  (0..3 = query, 4..7 = key)
  const int l0  = (blockIdx.x % bpt) * PJ_POS;
  const bool isQ = (tb < NB);
  const int b   = tb & 3;
  const float* __restrict__ src = isQ ? xq : xk;
  __nv_bfloat16* __restrict__ dst = isQ ? g_Q : g_K;

  for (int i = tid; i < NH*NC; i += 256){
    int j = i >> 6, c = i & 63;
    sm[SA_W1 + j*W1_PITCH + c] = W1[i];        // W1[j][c]
  }
  for (int i = tid; i < NC*NH; i += 256){
    int o = i >> 7, j = i & 127;
    sm[SA_W2 + o*W2_PITCH + j] = W2[i];        // W2[o][j]
  }
  for (int i = tid; i < NC*PJ_POS; i += 256){
    int p = i & 31, c = i >> 5;
    sm[SA_XS + p*XS_PITCH + c] = src[((size_t)b*NC + c)*NL + l0 + p];  // xs[p][c]
  }

  const int lanegrp = tid & 31;
  const int pg      = tid >> 5;

  __syncthreads();

  // ---- phase 1: h = leakyrelu(W1 @ x) ----
  {
    float acc[4][4];
    #pragma unroll
    for (int ji=0;ji<4;ji++)
      #pragma unroll
      for (int pi=0;pi<4;pi++) acc[ji][pi]=0.f;
    #pragma unroll 4
    for (int c4 = 0; c4 < NC; c4 += 4){
      float4 w[4], x[4];
      #pragma unroll
      for (int ji=0;ji<4;ji++)
        w[ji] = *(const float4*)&sm[SA_W1 + (lanegrp + ji*32)*W1_PITCH + c4];
      #pragma unroll
      for (int pi=0;pi<4;pi++)
        x[pi] = *(const float4*)&sm[SA_XS + (pg*4+pi)*XS_PITCH + c4];   // broadcast
      #pragma unroll
      for (int pi=0;pi<4;pi++)
        #pragma unroll
        for (int ji=0;ji<4;ji++){
          acc[ji][pi] += w[ji].x*x[pi].x + w[ji].y*x[pi].y
                       + w[ji].z*x[pi].z + w[ji].w*x[pi].w;
        }
    }
    #pragma unroll
    for (int pi=0;pi<4;pi++)
      #pragma unroll
      for (int ji=0;ji<4;ji++){
        float v = acc[ji][pi];
        v = v >= 0.f ? v : 0.01f*v;
        sm[SA_HS + (pg*4+pi)*HS_PITCH + lanegrp + ji*32] = v;   // hs[p][j]
      }
  }
  __syncthreads();

  // ---- phase 2: y = W2 @ h ; normalize ; split to bf16 ----
  {
    float acc[2][4];
    #pragma unroll
    for (int oi=0;oi<2;oi++)
      #pragma unroll
      for (int pi=0;pi<4;pi++) acc[oi][pi]=0.f;
    #pragma unroll 4
    for (int j4 = 0; j4 < NH; j4 += 4){
      float4 w0 = *(const float4*)&sm[SA_W2 + lanegrp*W2_PITCH + j4];
      float4 w1 = *(const float4*)&sm[SA_W2 + (lanegrp+32)*W2_PITCH + j4];
      #pragma unroll
      for (int pi=0;pi<4;pi++){
        float4 h = *(const float4*)&sm[SA_HS + (pg*4+pi)*HS_PITCH + j4]; // broadcast
        acc[0][pi] += w0.x*h.x + w0.y*h.y + w0.z*h.z + w0.w*h.w;
        acc[1][pi] += w1.x*h.x + w1.y*h.y + w1.z*h.z + w1.w*h.w;
      }
    }
    #pragma unroll
    for (int pi=0;pi<4;pi++){
      float ssq = acc[0][pi]*acc[0][pi] + acc[1][pi]*acc[1][pi];
      #pragma unroll
      for (int off=16; off; off>>=1) ssq += __shfl_xor_sync(0xffffffffu, ssq, off);
      float inv = 1.0f / fmaxf(sqrtf(ssq), 1e-12f);
      int p = pg*4 + pi;
      size_t rowbase = ((size_t)b*NL + l0 + p) * NKE;
      #pragma unroll
      for (int oi=0;oi<2;oi++){
        int o = lanegrp + oi*32;
        float v = acc[oi][pi] * inv;
        __nv_bfloat16 hi = __float2bfloat16(v);
        __nv_bfloat16 lo = __float2bfloat16(v - __bfloat162float(hi));
        if (isQ){
          dst[rowbase + o]       = hi;
          dst[rowbase + 64 + o]  = lo;
          dst[rowbase + 128 + o] = hi;
        } else {
          dst[rowbase + o]       = hi;
          dst[rowbase + 64 + o]  = hi;
          dst[rowbase + 128 + o] = lo;
        }
      }
    }
  }
}

// ----- attention: THREE independent warp-groups pipelined over chunk residues -----
#define ATH   384            // 12 warps: 3 groups x 4 row-warps
#define CHUNK 32             // key-cols per chunk
#define SROW_B 400           // padded smem row stride (192*2=384 data + 16 pad)
#define QTILE_B (128*SROW_B)           // 51200
#define KTILE_B (CHUNK*SROW_B)         // 12800
#define SQ_OFF  0
#define SKB(gr,s) (QTILE_B + ((gr)*3+(s))*KTILE_B)
#define SRS_OFF (QTILE_B + 9*KTILE_B)  // 166400: float rsum[3][128]
#define SINV_OFF (SRS_OFF + 1536)
#define SB_TOTAL (SINV_OFF + 512)      // 168448 B

__device__ __forceinline__ float fexp2(float x){
  float y;
  asm("ex2.approx.ftz.f32 %0, %1;" : "=f"(y) : "f"(x));
  return y;
}
__device__ __forceinline__ void cpa16(void* sptr, const void* gptr){
  uint32_t s = (uint32_t)__cvta_generic_to_shared(sptr);
  asm volatile("cp.async.cg.shared.global [%0], [%1], 16;" :: "r"(s), "l"(gptr));
}
__device__ __forceinline__ void cpcommit(){ asm volatile("cp.async.commit_group;"); }
__device__ __forceinline__ void cpwait1(){ asm volatile("cp.async.wait_group 1;"); }
__device__ __forceinline__ void groupbar(int id){
  asm volatile("bar.sync %0, 128;" :: "r"(id) : "memory");
}

__device__ __forceinline__ void ldsm4(uint32_t (&r)[4], uint32_t saddr){
  asm volatile("ldmatrix.sync.aligned.m8n8.x4.shared.b16 {%0,%1,%2,%3}, [%4];"
    : "=r"(r[0]), "=r"(r[1]), "=r"(r[2]), "=r"(r[3]) : "r"(saddr));
}
__device__ __forceinline__ void mma16816(float (&c)[4], const uint32_t (&a)[4],
                                         uint32_t b0, uint32_t b1){
  asm volatile(
    "mma.sync.aligned.m16n8k16.row.col.f32.bf16.bf16.f32 "
    "{%0,%1,%2,%3}, {%4,%5,%6,%7}, {%8,%9}, {%0,%1,%2,%3};"
    : "+f"(c[0]), "+f"(c[1]), "+f"(c[2]), "+f"(c[3])
    : "r"(a[0]), "r"(a[1]), "r"(a[2]), "r"(a[3]), "r"(b0), "r"(b1));
}

// stage 128 Q rows with 384 threads (3072 x 16B)
__device__ __forceinline__ void stage_q(char* sdst, const __nv_bfloat16* gsrc, int tid){
  const char* gb = (const char*)gsrc;
  #pragma unroll
  for (int i = 0; i < 8; i++){
    int idx = tid + i*ATH;
    int r = idx / 24, o = idx % 24;
    cpa16(sdst + r*SROW_B + o*16, gb + (size_t)r*384 + o*16);
  }
}
// stage 32 key rows with this group's 128 threads (768 x 16B)
__device__ __forceinline__ void stage_k(char* sdst, const __nv_bfloat16* gsrc, int gtid){
  const char* gb = (const char*)gsrc;
  #pragma unroll
  for (int i = 0; i < 6; i++){
    int idx = gtid + i*128;
    int r = idx / 24, o = idx % 24;
    cpa16(sdst + r*SROW_B + o*16, gb + (size_t)r*384 + o*16);
  }
}

__global__ void __launch_bounds__(ATH,1) attn_kernel(float* __restrict__ out){
  extern __shared__ char sm_c[];
  char* sm = sm_c;
  float* rsum = (float*)(sm + SRS_OFF);
  float* invp = (float*)(sm + SINV_OFF);

  const int tid = threadIdx.x;
  const int lane = tid & 31, wid = tid >> 5;
  const int gidx = wid >> 2;        // warp-group 0/1/2 (chunk residue class)
  const int gtid = tid & 127;
  const int wr = wid & 3;           // row-warp within group
  const int g = lane >> 2, t = lane & 3;
  const int barid = 1 + gidx;
  const int b = blockIdx.y, rb = blockIdx.x;

  const int NJg = (130 - gidx) / 3;  // 43,43,42 chunks per pass
  const int NJ2 = 2*NJg;

  const uint32_t smem_base = (uint32_t)__cvta_generic_to_shared(sm);

  const uint32_t aoff0 = (uint32_t)((wr*32 +  0 + (lane & 15))*SROW_B + ((lane >> 4) & 1)*16);
  const uint32_t aoff1 = (uint32_t)((wr*32 + 16 + (lane & 15))*SROW_B + ((lane >> 4) & 1)*16);
  const uint32_t boff = (uint32_t)(((lane & 7) + ((lane >> 1) & 8))*SROW_B + (lane & 8)*2);

  const __nv_bfloat16* Qg = g_Q + ((size_t)b*NL + (size_t)rb*128)*NKE;
  const __nv_bfloat16* Kg = g_K + (size_t)b*NL*NKE;

  stage_q(sm + SQ_OFF, Qg, tid);
  stage_k(sm + SKB(gidx,0), Kg + (size_t)(gidx)*CHUNK*NKE, gtid);
  cpcommit();
  stage_k(sm + SKB(gidx,1), Kg + (size_t)(gidx+3)*CHUNK*NKE, gtid);
  cpcommit();
  cpwait1();
  __syncthreads();

  uint32_t afr[12][2][4];
  {
    const uint32_t aA0 = smem_base + SQ_OFF + aoff0;
    const uint32_t aA1 = smem_base + SQ_OFF + aoff1;
    #pragma unroll
    for (int ks = 0; ks < 12; ks++){
      ldsm4(afr[ks][0], aA0 + ks*32);
      ldsm4(afr[ks][1], aA1 + ks*32);
    }
  }

  float esum[2][2] = {{0.f,0.f},{0.f,0.f}};
  float vinv[2][2] = {{0.f,0.f},{0.f,0.f}};

  for (int j = 0; j < NJ2; j++){
    if (j > 0){
      cpwait1();
      groupbar(barid);
    }
    {
      int nx = j + 2;
      if (nx < NJ2){
        int cg = gidx + 3*(nx >= NJg ? nx - NJg : nx);
        stage_k(sm + SKB(gidx, nx % 3), Kg + (size_t)cg*CHUNK*NKE, gtid);
      }
      cpcommit();
    }

    const uint32_t bB = smem_base + SKB(gidx, j % 3) + boff;

    float acc[2][4][4];
    #pragma unroll
    for (int mt=0;mt<2;mt++)
      #pragma unroll
      for (int nt=0;nt<4;nt++)
        #pragma unroll
        for (int i=0;i<4;i++) acc[mt][nt][i]=0.f;

    #pragma unroll
    for (int ks = 0; ks < 12; ks++){
      uint32_t br0[4], br1[4];
      ldsm4(br0, bB + ks*32);
      ldsm4(br1, bB + 16*SROW_B + ks*32);
      mma16816(acc[0][0], afr[ks][0], br0[0], br0[1]);
      mma16816(acc[1][0], afr[ks][1], br0[0], br0[1]);
      mma16816(acc[0][1], afr[ks][0], br0[2], br0[3]);
      mma16816(acc[1][1], afr[ks][1], br0[2], br0[3]);
      mma16816(acc[0][2], afr[ks][0], br1[0], br1[1]);
      mma16816(acc[1][2], afr[ks][1], br1[0], br1[1]);
      mma16816(acc[0][3], afr[ks][0], br1[2], br1[3]);
      mma16816(acc[1][3], afr[ks][1], br1[2], br1[3]);
    }

    if (j < NJg){
      #pragma unroll
      for (int mt=0;mt<2;mt++)
        #pragma unroll
        for (int nt=0;nt<4;nt++){
          esum[mt][0] += fexp2(acc[mt][nt][0]*SCALE_LOG2E) + fexp2(acc[mt][nt][1]*SCALE_LOG2E);
          esum[mt][1] += fexp2(acc[mt][nt][2]*SCALE_LOG2E) + fexp2(acc[mt][nt][3]*SCALE_LOG2E);
        }
    } else {
      int cg = gidx + 3*(j - NJg);
      #pragma unroll
      for (int mt=0;mt<2;mt++){
        int r0 = rb*128 + wr*32 + mt*16 + g;
        float* o0 = out + ((size_t)b*NL + r0)*NL + cg*CHUNK + t*2;
        float* o1 = o0 + (size_t)8*NL;
        #pragma unroll
        for (int nt=0;nt<4;nt++){
          float w00 = fexp2(acc[mt][nt][0]*SCALE_LOG2E)*vinv[mt][0];
          float w01 = fexp2(acc[mt][nt][1]*SCALE_LOG2E)*vinv[mt][0];
          float w10 = fexp2(acc[mt][nt][2]*SCALE_LOG2E)*vinv[mt][1];
          float w11 = fexp2(acc[mt][nt][3]*SCALE_LOG2E)*vinv[mt][1];
          float2 v0 = make_float2(w00 > THRESH ? w00 : 0.f, w01 > THRESH ? w01 : 0.f);
          float2 v1 = make_float2(w10 > THRESH ? w10 : 0.f, w11 > THRESH ? w11 : 0.f);
          *(float2*)(o0 + nt*8) = v0;
          *(float2*)(o1 + nt*8) = v1;
        }
      }
    }

    if (j == NJg-1){
      #pragma unroll
      for (int mt=0;mt<2;mt++)
        #pragma unroll
        for (int hh=0;hh<2;hh++){
          float v = esum[mt][hh];
          v += __shfl_xor_sync(0xffffffffu, v, 1);
          v += __shfl_xor_sync(0xffffffffu, v, 2);
          esum[mt][hh] = v;
        }
      if (t == 0){
        #pragma unroll
        for (int mt=0;mt<2;mt++){
          rsum[gidx*128 + wr*32 + mt*16 + g]     = esum[mt][0];
          rsum[gidx*128 + wr*32 + mt*16 + g + 8] = esum[mt][1];
        }
      }
      __syncthreads();
      if (tid < 128) invp[tid] = 1.0f / (rsum[tid] + rsum[128 + tid] + rsum[256 + tid]);
      __syncthreads();
      #pragma unroll
      for (int mt=0;mt<2;mt++){
        vinv[mt][0] = invp[wr*32 + mt*16 + g];
        vinv[mt][1] = invp[wr*32 + mt*16 + g + 8];
      }
    }
  }
}

// ---------------- launch ----------------
extern "C" void kernel_launch(void* const* d_in, const int* in_sizes, int n_in,
                              void* d_out, int out_size){
  const float* q  = (const float*)d_in[0];
  const float* k  = (const float*)d_in[1];
  const float* W1 = (const float*)d_in[2];
  const float* W2 = (const float*)d_in[3];
  float* out = (float*)d_out;

  cudaFuncSetAttribute(proj_kernel, cudaFuncAttributeMaxDynamicSharedMemorySize, SA_BYTES);
  cudaFuncSetAttribute(attn_kernel, cudaFuncAttributeMaxDynamicSharedMemorySize, SB_TOTAL);

  proj_kernel<<<2*NB*NL/PJ_POS, 256, SA_BYTES>>>(q, k, W1, W2);
  attn_kernel<<<dim3(NL/128, NB), ATH, SB_TOTAL>>>(out);
}

// round 15
// speedup vs baseline: 1.0788x; 1.0788x over previous
#include <cuda_runtime.h>
#include <cuda_bf16.h>
#include <cstdint>
#include <cstddef>

#define NB   4
#define NC   64
#define NL   4096
#define NH   128
#define NKE  192          // [hi|x|x] split-bf16 extended K dimension

#define SCALE_LOG2E 14.4269504088896340737f   // 10 * log2(e)
#define THRESH 1e-3f

// ---------------- device scratch (no allocations allowed) ----------------
__device__ __align__(256) __nv_bfloat16 g_Q[NB*NL*NKE];   // [b][l][192] = [qhi|qlo|qhi]
__device__ __align__(256) __nv_bfloat16 g_K[NB*NL*NKE];   // [b][l][192] = [khi|khi|klo]

// ---------------- projection + leakyrelu + projection + l2norm + bf16 split ----------------
#define PJ_POS 32
#define PJ_GROUPS 4
#define W1_PITCH 68    // [j][c]
#define W2_PITCH 132   // [o][j]
#define XS_PITCH 68    // [p][c]
#define HS_PITCH 132   // [p][j]
#define SA_W1 0
#define SA_W2 (NH*W1_PITCH)                  // 8704
#define SA_XS (SA_W2 + NC*W2_PITCH)          // 17152
#define SA_HS (SA_XS + PJ_POS*XS_PITCH)      // 19328
#define SA_FLOATS (SA_HS + PJ_POS*HS_PITCH)  // 23552
#define SA_BYTES (SA_FLOATS*4)               // 94208

__global__ void __launch_bounds__(256,2) proj_kernel(const float* __restrict__ xq,
                                                     const float* __restrict__ xk,
                                                     const float* __restrict__ W1,
                                                     const float* __restrict__ W2){
  extern __shared__ float sm_f[];
  float* sm = sm_f;
  const int tid = threadIdx.x;
  const int bpt = NL / (PJ_POS*PJ_GROUPS);     // 32 blocks per (tensor,batch)
  const int tb  = blockIdx.x / bpt;            // 0..7  (0..3 = query, 4..7 = key)
  const int base = (blockIdx.x % bpt) * (PJ_POS*PJ_GROUPS);
  const bool isQ = (tb < NB);
  const int b   = tb & 3;
  const float* __restrict__ src = isQ ? xq : xk;
  __nv_bfloat16* __restrict__ dst = isQ ? g_Q : g_K;

  // weights staged ONCE per CTA (amortized over 128 positions)
  for (int i = tid; i < NH*NC; i += 256){
    int j = i >> 6, c = i & 63;
    sm[SA_W1 + j*W1_PITCH + c] = W1[i];        // W1[j][c]
  }
  for (int i = tid; i < NC*NH; i += 256){
    int o = i >> 7, j = i & 127;
    sm[SA_W2 + o*W2_PITCH + j] = W2[i];        // W2[o][j]
  }

  const int lanegrp = tid & 31;
  const int pg      = tid >> 5;

  for (int grp = 0; grp < PJ_GROUPS; grp++){
    const int l0 = base + grp*PJ_POS;
    __syncthreads();   // W ready (first iter) / previous phase2 done reading HS/XS
    for (int i = tid; i < NC*PJ_POS; i += 256){
      int p = i & 31, c = i >> 5;
      sm[SA_XS + p*XS_PITCH + c] = src[((size_t)b*NC + c)*NL + l0 + p];  // xs[p][c]
    }
    __syncthreads();

    // ---- phase 1: h = leakyrelu(W1 @ x) ----
    {
      float acc[4][4];
      #pragma unroll
      for (int ji=0;ji<4;ji++)
        #pragma unroll
        for (int pi=0;pi<4;pi++) acc[ji][pi]=0.f;
      #pragma unroll 4
      for (int c4 = 0; c4 < NC; c4 += 4){
        float4 w[4], x[4];
        #pragma unroll
        for (int ji=0;ji<4;ji++)
          w[ji] = *(const float4*)&sm[SA_W1 + (lanegrp + ji*32)*W1_PITCH + c4];
        #pragma unroll
        for (int pi=0;pi<4;pi++)
          x[pi] = *(const float4*)&sm[SA_XS + (pg*4+pi)*XS_PITCH + c4];   // broadcast
        #pragma unroll
        for (int pi=0;pi<4;pi++)
          #pragma unroll
          for (int ji=0;ji<4;ji++){
            acc[ji][pi] += w[ji].x*x[pi].x + w[ji].y*x[pi].y
                         + w[ji].z*x[pi].z + w[ji].w*x[pi].w;
          }
      }
      #pragma unroll
      for (int pi=0;pi<4;pi++)
        #pragma unroll
        for (int ji=0;ji<4;ji++){
          float v = acc[ji][pi];
          v = v >= 0.f ? v : 0.01f*v;
          sm[SA_HS + (pg*4+pi)*HS_PITCH + lanegrp + ji*32] = v;   // hs[p][j]
        }
    }
    __syncthreads();

    // ---- phase 2: y = W2 @ h ; normalize ; split to bf16 ----
    {
      float acc[2][4];
      #pragma unroll
      for (int oi=0;oi<2;oi++)
        #pragma unroll
        for (int pi=0;pi<4;pi++) acc[oi][pi]=0.f;
      #pragma unroll 4
      for (int j4 = 0; j4 < NH; j4 += 4){
        float4 w0 = *(const float4*)&sm[SA_W2 + lanegrp*W2_PITCH + j4];
        float4 w1 = *(const float4*)&sm[SA_W2 + (lanegrp+32)*W2_PITCH + j4];
        #pragma unroll
        for (int pi=0;pi<4;pi++){
          float4 h = *(const float4*)&sm[SA_HS + (pg*4+pi)*HS_PITCH + j4]; // broadcast
          acc[0][pi] += w0.x*h.x + w0.y*h.y + w0.z*h.z + w0.w*h.w;
          acc[1][pi] += w1.x*h.x + w1.y*h.y + w1.z*h.z + w1.w*h.w;
        }
      }
      #pragma unroll
      for (int pi=0;pi<4;pi++){
        float ssq = acc[0][pi]*acc[0][pi] + acc[1][pi]*acc[1][pi];
        #pragma unroll
        for (int off=16; off; off>>=1) ssq += __shfl_xor_sync(0xffffffffu, ssq, off);
        float inv = 1.0f / fmaxf(sqrtf(ssq), 1e-12f);
        int p = pg*4 + pi;
        size_t rowbase = ((size_t)b*NL + l0 + p) * NKE;
        #pragma unroll
        for (int oi=0;oi<2;oi++){
          int o = lanegrp + oi*32;
          float v = acc[oi][pi] * inv;
          __nv_bfloat16 hi = __float2bfloat16(v);
          __nv_bfloat16 lo = __float2bfloat16(v - __bfloat162float(hi));
          if (isQ){
            dst[rowbase + o]       = hi;
            dst[rowbase + 64 + o]  = lo;
            dst[rowbase + 128 + o] = hi;
          } else {
            dst[rowbase + o]       = hi;
            dst[rowbase + 64 + o]  = hi;
            dst[rowbase + 128 + o] = lo;
          }
        }
      }
    }
  }
}

// ----- attention: THREE independent warp-groups pipelined over chunk residues -----
#define ATH   384            // 12 warps: 3 groups x 4 row-warps
#define CHUNK 32             // key-cols per chunk
#define SROW_B 400           // padded smem row stride (192*2=384 data + 16 pad)
#define QTILE_B (128*SROW_B)           // 51200
#define KTILE_B (CHUNK*SROW_B)         // 12800
#define SQ_OFF  0
#define SKB(gr,s) (QTILE_B + ((gr)*3+(s))*KTILE_B)
#define SRS_OFF (QTILE_B + 9*KTILE_B)  // 166400: float rsum[3][128]
#define SINV_OFF (SRS_OFF + 1536)
#define SB_TOTAL (SINV_OFF + 512)      // 168448 B

__device__ __forceinline__ float fexp2(float x){
  float y;
  asm("ex2.approx.ftz.f32 %0, %1;" : "=f"(y) : "f"(x));
  return y;
}
__device__ __forceinline__ void cpa16(void* sptr, const void* gptr){
  uint32_t s = (uint32_t)__cvta_generic_to_shared(sptr);
  asm volatile("cp.async.cg.shared.global [%0], [%1], 16;" :: "r"(s), "l"(gptr));
}
__device__ __forceinline__ void cpcommit(){ asm volatile("cp.async.commit_group;"); }
__device__ __forceinline__ void cpwait1(){ asm volatile("cp.async.wait_group 1;"); }
__device__ __forceinline__ void groupbar(int id){
  asm volatile("bar.sync %0, 128;" :: "r"(id) : "memory");
}

__device__ __forceinline__ void ldsm4(uint32_t (&r)[4], uint32_t saddr){
  asm volatile("ldmatrix.sync.aligned.m8n8.x4.shared.b16 {%0,%1,%2,%3}, [%4];"
    : "=r"(r[0]), "=r"(r[1]), "=r"(r[2]), "=r"(r[3]) : "r"(saddr));
}
__device__ __forceinline__ void mma16816(float (&c)[4], const uint32_t (&a)[4],
                                         uint32_t b0, uint32_t b1){
  asm volatile(
    "mma.sync.aligned.m16n8k16.row.col.f32.bf16.bf16.f32 "
    "{%0,%1,%2,%3}, {%4,%5,%6,%7}, {%8,%9}, {%0,%1,%2,%3};"
    : "+f"(c[0]), "+f"(c[1]), "+f"(c[2]), "+f"(c[3])
    : "r"(a[0]), "r"(a[1]), "r"(a[2]), "r"(a[3]), "r"(b0), "r"(b1));
}

// stage 128 Q rows with 384 threads (3072 x 16B)
__device__ __forceinline__ void stage_q(char* sdst, const __nv_bfloat16* gsrc, int tid){
  const char* gb = (const char*)gsrc;
  #pragma unroll
  for (int i = 0; i < 8; i++){
    int idx = tid + i*ATH;
    int r = idx / 24, o = idx % 24;
    cpa16(sdst + r*SROW_B + o*16, gb + (size_t)r*384 + o*16);
  }
}
// stage 32 key rows with this group's 128 threads (768 x 16B)
__device__ __forceinline__ void stage_k(char* sdst, const __nv_bfloat16* gsrc, int gtid){
  const char* gb = (const char*)gsrc;
  #pragma unroll
  for (int i = 0; i < 6; i++){
    int idx = gtid + i*128;
    int r = idx / 24, o = idx % 24;
    cpa16(sdst + r*SROW_B + o*16, gb + (size_t)r*384 + o*16);
  }
}

__global__ void __launch_bounds__(ATH,1) attn_kernel(float* __restrict__ out){
  extern __shared__ char sm_c[];
  char* sm = sm_c;
  float* rsum = (float*)(sm + SRS_OFF);
  float* invp = (float*)(sm + SINV_OFF);

  const int tid = threadIdx.x;
  const int lane = tid & 31, wid = tid >> 5;
  const int gidx = wid >> 2;        // warp-group 0/1/2 (chunk residue class)
  const int gtid = tid & 127;
  const int wr = wid & 3;           // row-warp within group
  const int g = lane >> 2, t = lane & 3;
  const int barid = 1 + gidx;
  const int b = blockIdx.y, rb = blockIdx.x;

  const int NJg = (130 - gidx) / 3;  // 43,43,42 chunks per pass
  const int NJ2 = 2*NJg;

  const uint32_t smem_base = (uint32_t)__cvta_generic_to_shared(sm);

  const uint32_t aoff0 = (uint32_t)((wr*32 +  0 + (lane & 15))*SROW_B + ((lane >> 4) & 1)*16);
  const uint32_t aoff1 = (uint32_t)((wr*32 + 16 + (lane & 15))*SROW_B + ((lane >> 4) & 1)*16);
  const uint32_t boff = (uint32_t)(((lane & 7) + ((lane >> 1) & 8))*SROW_B + (lane & 8)*2);

  const __nv_bfloat16* Qg = g_Q + ((size_t)b*NL + (size_t)rb*128)*NKE;
  const __nv_bfloat16* Kg = g_K + (size_t)b*NL*NKE;

  stage_q(sm + SQ_OFF, Qg, tid);
  stage_k(sm + SKB(gidx,0), Kg + (size_t)(gidx)*CHUNK*NKE, gtid);
  cpcommit();
  stage_k(sm + SKB(gidx,1), Kg + (size_t)(gidx+3)*CHUNK*NKE, gtid);
  cpcommit();
  cpwait1();
  __syncthreads();

  uint32_t afr[12][2][4];
  {
    const uint32_t aA0 = smem_base + SQ_OFF + aoff0;
    const uint32_t aA1 = smem_base + SQ_OFF + aoff1;
    #pragma unroll
    for (int ks = 0; ks < 12; ks++){
      ldsm4(afr[ks][0], aA0 + ks*32);
      ldsm4(afr[ks][1], aA1 + ks*32);
    }
  }

  float esum[2][2] = {{0.f,0.f},{0.f,0.f}};
  float vinv[2][2] = {{0.f,0.f},{0.f,0.f}};

  for (int j = 0; j < NJ2; j++){
    if (j > 0){
      cpwait1();
      groupbar(barid);
    }
    {
      int nx = j + 2;
      if (nx < NJ2){
        int cg = gidx + 3*(nx >= NJg ? nx - NJg : nx);
        stage_k(sm + SKB(gidx, nx % 3), Kg + (size_t)cg*CHUNK*NKE, gtid);
      }
      cpcommit();
    }

    const uint32_t bB = smem_base + SKB(gidx, j % 3) + boff;

    float acc[2][4][4];
    #pragma unroll
    for (int mt=0;mt<2;mt++)
      #pragma unroll
      for (int nt=0;nt<4;nt++)
        #pragma unroll
        for (int i=0;i<4;i++) acc[mt][nt][i]=0.f;

    #pragma unroll
    for (int ks = 0; ks < 12; ks++){
      uint32_t br0[4], br1[4];
      ldsm4(br0, bB + ks*32);
      ldsm4(br1, bB + 16*SROW_B + ks*32);
      mma16816(acc[0][0], afr[ks][0], br0[0], br0[1]);
      mma16816(acc[1][0], afr[ks][1], br0[0], br0[1]);
      mma16816(acc[0][1], afr[ks][0], br0[2], br0[3]);
      mma16816(acc[1][1], afr[ks][1], br0[2], br0[3]);
      mma16816(acc[0][2], afr[ks][0], br1[0], br1[1]);
      mma16816(acc[1][2], afr[ks][1], br1[0], br1[1]);
      mma16816(acc[0][3], afr[ks][0], br1[2], br1[3]);
      mma16816(acc[1][3], afr[ks][1], br1[2], br1[3]);
    }

    if (j < NJg){
      #pragma unroll
      for (int mt=0;mt<2;mt++)
        #pragma unroll
        for (int nt=0;nt<4;nt++){
          esum[mt][0] += fexp2(acc[mt][nt][0]*SCALE_LOG2E) + fexp2(acc[mt][nt][1]*SCALE_LOG2E);
          esum[mt][1] += fexp2(acc[mt][nt][2]*SCALE_LOG2E) + fexp2(acc[mt][nt][3]*SCALE_LOG2E);
        }
    } else {
      int cg = gidx + 3*(j - NJg);
      #pragma unroll
      for (int mt=0;mt<2;mt++){
        int r0 = rb*128 + wr*32 + mt*16 + g;
        float* o0 = out + ((size_t)b*NL + r0)*NL + cg*CHUNK + t*2;
        float* o1 = o0 + (size_t)8*NL;
        #pragma unroll
        for (int nt=0;nt<4;nt++){
          float w00 = fexp2(acc[mt][nt][0]*SCALE_LOG2E)*vinv[mt][0];
          float w01 = fexp2(acc[mt][nt][1]*SCALE_LOG2E)*vinv[mt][0];
          float w10 = fexp2(acc[mt][nt][2]*SCALE_LOG2E)*vinv[mt][1];
          float w11 = fexp2(acc[mt][nt][3]*SCALE_LOG2E)*vinv[mt][1];
          float2 v0 = make_float2(w00 > THRESH ? w00 : 0.f, w01 > THRESH ? w01 : 0.f);
          float2 v1 = make_float2(w10 > THRESH ? w10 : 0.f, w11 > THRESH ? w11 : 0.f);
          *(float2*)(o0 + nt*8) = v0;
          *(float2*)(o1 + nt*8) = v1;
        }
      }
    }

    if (j == NJg-1){
      #pragma unroll
      for (int mt=0;mt<2;mt++)
        #pragma unroll
        for (int hh=0;hh<2;hh++){
          float v = esum[mt][hh];
          v += __shfl_xor_sync(0xffffffffu, v, 1);
          v += __shfl_xor_sync(0xffffffffu, v, 2);
          esum[mt][hh] = v;
        }
      if (t == 0){
        #pragma unroll
        for (int mt=0;mt<2;mt++){
          rsum[gidx*128 + wr*32 + mt*16 + g]     = esum[mt][0];
          rsum[gidx*128 + wr*32 + mt*16 + g + 8] = esum[mt][1];
        }
      }
      __syncthreads();
      if (tid < 128) invp[tid] = 1.0f / (rsum[tid] + rsum[128 + tid] + rsum[256 + tid]);
      __syncthreads();
      #pragma unroll
      for (int mt=0;mt<2;mt++){
        vinv[mt][0] = invp[wr*32 + mt*16 + g];
        vinv[mt][1] = invp[wr*32 + mt*16 + g + 8];
      }
    }
  }
}

// ---------------- launch ----------------
extern "C" void kernel_launch(void* const* d_in, const int* in_sizes, int n_in,
                              void* d_out, int out_size){
  const float* q  = (const float*)d_in[0];
  const float* k  = (const float*)d_in[1];
  const float* W1 = (const float*)d_in[2];
  const float* W2 = (const float*)d_in[3];
  float* out = (float*)d_out;

  cudaFuncSetAttribute(proj_kernel, cudaFuncAttributeMaxDynamicSharedMemorySize, SA_BYTES);
  cudaFuncSetAttribute(attn_kernel, cudaFuncAttributeMaxDynamicSharedMemorySize, SB_TOTAL);

  proj_kernel<<<2*NB*NL/(PJ_POS*PJ_GROUPS), 256, SA_BYTES>>>(q, k, W1, W2);
  attn_kernel<<<dim3(NL/128, NB), ATH, SB_TOTAL>>>(out);
}

// round 16
// speedup vs baseline: 1.0888x; 1.0092x over previous
#include <cuda_runtime.h>
#include <cuda_bf16.h>
#include <cstdint>
#include <cstddef>

#define NB   4
#define NC   64
#define NL   4096
#define NH   128
#define NKE  192          // [hi|x|x] split-bf16 extended K dimension

#define SCALE_LOG2E 14.4269504088896340737f   // 10 * log2(e)
#define THRESH 1e-3f

typedef unsigned long long ull;

// ---------------- device scratch (no allocations allowed) ----------------
__device__ __align__(256) __nv_bfloat16 g_Q[NB*NL*NKE];   // [b][l][192] = [qhi|qlo|qhi]
__device__ __align__(256) __nv_bfloat16 g_K[NB*NL*NKE];   // [b][l][192] = [khi|khi|klo]

// ---------------- packed f32x2 helpers ----------------
#define FMA_F32X2(d, a, b, c) \
  asm("fma.rn.f32x2 %0, %1, %2, %3;" : "=l"(d) : "l"(a), "l"(b), "l"(c))
#define PACK_F32X2(out, lo, hi) \
  asm("mov.b64 %0, {%1, %2};" : "=l"(out) : "f"(lo), "f"(hi))
#define UNPACK_F32X2(lo, hi, in) \
  asm("mov.b64 {%0, %1}, %2;" : "=f"(lo), "=f"(hi) : "l"(in))

// ---------------- projection: f32x2-packed FMA, warp-private phases ----------------
#define PJ_POS 32
#define PJ_GROUPS 4
#define W1T_PITCH 132   // [c][j] (j=128 + pad)
#define W2_PITCH 132    // [o][j]
#define XS_PITCH 68     // [p][c]
#define HS2_PITCH 36    // [j][p] (p=32 + pad, 144B rows: 16B-aligned)
#define SA_W1T 0
#define SA_W2  (NC*W1T_PITCH)                  // 8448
#define SA_XS  (SA_W2 + NC*W2_PITCH)           // 16896
#define SA_HS2 (SA_XS + PJ_POS*XS_PITCH)       // 19072
#define SA_FLOATS (SA_HS2 + NH*HS2_PITCH)      // 23680
#define SA_BYTES (SA_FLOATS*4)                 // 94720

__global__ void __launch_bounds__(256,2) proj_kernel(const float* __restrict__ xq,
                                                     const float* __restrict__ xk,
                                                     const float* __restrict__ W1,
                                                     const float* __restrict__ W2){
  extern __shared__ float sm_f[];
  float* sm = sm_f;
  const int tid = threadIdx.x;
  const int bpt = NL / (PJ_POS*PJ_GROUPS);     // 32 blocks per (tensor,batch)
  const int tb  = blockIdx.x / bpt;            // 0..7  (0..3 = query, 4..7 = key)
  const int base = (blockIdx.x % bpt) * (PJ_POS*PJ_GROUPS);
  const bool isQ = (tb < NB);
  const int b   = tb & 3;
  const float* __restrict__ src = isQ ? xq : xk;
  __nv_bfloat16* __restrict__ dst = isQ ? g_Q : g_K;

  // weights staged ONCE per CTA (W1 transposed to [c][j]; coalesced global reads)
  for (int i = tid; i < NH*NC; i += 256){
    int j = i >> 6, c = i & 63;
    sm[SA_W1T + c*W1T_PITCH + j] = W1[i];      // W1t[c][j]
  }
  for (int i = tid; i < NC*NH; i += 256){
    int o = i >> 7, j = i & 127;
    sm[SA_W2 + o*W2_PITCH + j] = W2[i];        // W2[o][j]
  }

  const int lanegrp = tid & 31;
  const int pg      = tid >> 5;

  for (int grp = 0; grp < PJ_GROUPS; grp++){
    const int l0 = base + grp*PJ_POS;
    __syncthreads();   // W ready (first iter) / previous group done with XS/HS
    for (int i = tid; i < NC*PJ_POS; i += 256){
      int p = i & 31, c = i >> 5;
      sm[SA_XS + p*XS_PITCH + c] = src[((size_t)b*NC + c)*NL + l0 + p];  // xs[p][c]
    }
    __syncthreads();

    // ---- phase 1: h = leakyrelu(W1 @ x) ----
    // lane owns 4 consecutive j = lanegrp*4..+3 (two f32x2 pairs); warp owns pos pg*4..+3
    {
      ull accp[2][4];   // [jpair][pi]
      #pragma unroll
      for (int jp=0;jp<2;jp++)
        #pragma unroll
        for (int pi=0;pi<4;pi++) accp[jp][pi] = 0ull;

      #pragma unroll 4
      for (int c4 = 0; c4 < NC; c4 += 4){
        float4 xv[4];
        #pragma unroll
        for (int pi=0;pi<4;pi++)
          xv[pi] = *(const float4*)&sm[SA_XS + (pg*4+pi)*XS_PITCH + c4];   // broadcast
        #pragma unroll
        for (int cc=0;cc<3+1;cc++){
          const float4 wv = *(const float4*)&sm[SA_W1T + (c4+cc)*W1T_PITCH + lanegrp*4];
          ull w01 = ((const ull*)&wv)[0];   // (j+0, j+1) pre-packed
          ull w23 = ((const ull*)&wv)[1];   // (j+2, j+3)
          #pragma unroll
          for (int pi=0;pi<4;pi++){
            float xsv = (cc==0) ? xv[pi].x : (cc==1) ? xv[pi].y : (cc==2) ? xv[pi].z : xv[pi].w;
            ull s; PACK_F32X2(s, xsv, xsv);
            FMA_F32X2(accp[0][pi], w01, s, accp[0][pi]);
            FMA_F32X2(accp[1][pi], w23, s, accp[1][pi]);
          }
        }
      }
      // unpack + leakyrelu + store hs[j][p] (float4 over positions)
      #pragma unroll
      for (int jp=0;jp<2;jp++){
        float hv0[4], hv1[4];
        #pragma unroll
        for (int pi=0;pi<4;pi++){
          float lo, hi;
          UNPACK_F32X2(lo, hi, accp[jp][pi]);
          lo = lo >= 0.f ? lo : 0.01f*lo;
          hi = hi >= 0.f ? hi : 0.01f*hi;
          hv0[pi] = lo; hv1[pi] = hi;
        }
        int j0 = lanegrp*4 + jp*2;
        *(float4*)&sm[SA_HS2 + j0*HS2_PITCH + pg*4]     = make_float4(hv0[0],hv0[1],hv0[2],hv0[3]);
        *(float4*)&sm[SA_HS2 + (j0+1)*HS2_PITCH + pg*4] = make_float4(hv1[0],hv1[1],hv1[2],hv1[3]);
      }
    }
    __syncwarp();   // h rows for warp pg are warp-private: no CTA barrier needed

    // ---- phase 2: y = W2 @ h ; normalize ; split to bf16 ----
    // lane owns o = lanegrp, lanegrp+32; positions packed in pairs
    {
      ull acc2p[2][2];   // [oi][pp]
      acc2p[0][0]=0ull; acc2p[0][1]=0ull; acc2p[1][0]=0ull; acc2p[1][1]=0ull;

      #pragma unroll 4
      for (int j4 = 0; j4 < NH; j4 += 4){
        const float4 w0 = *(const float4*)&sm[SA_W2 + lanegrp*W2_PITCH + j4];
        const float4 w1 = *(const float4*)&sm[SA_W2 + (lanegrp+32)*W2_PITCH + j4];
        #pragma unroll
        for (int jj=0;jj<4;jj++){
          int j = j4 + jj;
          ull h01 = *(const ull*)&sm[SA_HS2 + j*HS2_PITCH + pg*4];      // (p0,p1) packed
          ull h23 = *(const ull*)&sm[SA_HS2 + j*HS2_PITCH + pg*4 + 2];  // (p2,p3)
          float w0j = (jj==0) ? w0.x : (jj==1) ? w0.y : (jj==2) ? w0.z : w0.w;
          float w1j = (jj==0) ? w1.x : (jj==1) ? w1.y : (jj==2) ? w1.z : w1.w;
          ull s0, s1;
          PACK_F32X2(s0, w0j, w0j);
          PACK_F32X2(s1, w1j, w1j);
          FMA_F32X2(acc2p[0][0], s0, h01, acc2p[0][0]);
          FMA_F32X2(acc2p[0][1], s0, h23, acc2p[0][1]);
          FMA_F32X2(acc2p[1][0], s1, h01, acc2p[1][0]);
          FMA_F32X2(acc2p[1][1], s1, h23, acc2p[1][1]);
        }
      }
      // unpack to acc[oi][pi]
      float acc[2][4];
      #pragma unroll
      for (int oi=0;oi<2;oi++)
        #pragma unroll
        for (int pp=0;pp<2;pp++){
          float lo, hi;
          UNPACK_F32X2(lo, hi, acc2p[oi][pp]);
          acc[oi][2*pp]   = lo;
          acc[oi][2*pp+1] = hi;
        }
      #pragma unroll
      for (int pi=0;pi<4;pi++){
        float ssq = acc[0][pi]*acc[0][pi] + acc[1][pi]*acc[1][pi];
        #pragma unroll
        for (int off=16; off; off>>=1) ssq += __shfl_xor_sync(0xffffffffu, ssq, off);
        float inv = 1.0f / fmaxf(sqrtf(ssq), 1e-12f);
        int p = pg*4 + pi;
        size_t rowbase = ((size_t)b*NL + l0 + p) * NKE;
        #pragma unroll
        for (int oi=0;oi<2;oi++){
          int o = lanegrp + oi*32;
          float v = acc[oi][pi] * inv;
          __nv_bfloat16 hi = __float2bfloat16(v);
          __nv_bfloat16 lo = __float2bfloat16(v - __bfloat162float(hi));
          if (isQ){
            dst[rowbase + o]       = hi;
            dst[rowbase + 64 + o]  = lo;
            dst[rowbase + 128 + o] = hi;
          } else {
            dst[rowbase + o]       = hi;
            dst[rowbase + 64 + o]  = hi;
            dst[rowbase + 128 + o] = lo;
          }
        }
      }
    }
  }
}

// ----- attention: THREE independent warp-groups pipelined over chunk residues -----
#define ATH   384            // 12 warps: 3 groups x 4 row-warps
#define CHUNK 32             // key-cols per chunk
#define SROW_B 400           // padded smem row stride (192*2=384 data + 16 pad)
#define QTILE_B (128*SROW_B)           // 51200
#define KTILE_B (CHUNK*SROW_B)         // 12800
#define SQ_OFF  0
#define SKB(gr,s) (QTILE_B + ((gr)*3+(s))*KTILE_B)
#define SRS_OFF (QTILE_B + 9*KTILE_B)  // 166400: float rsum[3][128]
#define SINV_OFF (SRS_OFF + 1536)
#define SB_TOTAL (SINV_OFF + 512)      // 168448 B

__device__ __forceinline__ float fexp2(float x){
  float y;
  asm("ex2.approx.ftz.f32 %0, %1;" : "=f"(y) : "f"(x));
  return y;
}
__device__ __forceinline__ void cpa16(void* sptr, const void* gptr){
  uint32_t s = (uint32_t)__cvta_generic_to_shared(sptr);
  asm volatile("cp.async.cg.shared.global [%0], [%1], 16;" :: "r"(s), "l"(gptr));
}
__device__ __forceinline__ void cpcommit(){ asm volatile("cp.async.commit_group;"); }
__device__ __forceinline__ void cpwait1(){ asm volatile("cp.async.wait_group 1;"); }
__device__ __forceinline__ void groupbar(int id){
  asm volatile("bar.sync %0, 128;" :: "r"(id) : "memory");
}

__device__ __forceinline__ void ldsm4(uint32_t (&r)[4], uint32_t saddr){
  asm volatile("ldmatrix.sync.aligned.m8n8.x4.shared.b16 {%0,%1,%2,%3}, [%4];"
    : "=r"(r[0]), "=r"(r[1]), "=r"(r[2]), "=r"(r[3]) : "r"(saddr));
}
__device__ __forceinline__ void mma16816(float (&c)[4], const uint32_t (&a)[4],
                                         uint32_t b0, uint32_t b1){
  asm volatile(
    "mma.sync.aligned.m16n8k16.row.col.f32.bf16.bf16.f32 "
    "{%0,%1,%2,%3}, {%4,%5,%6,%7}, {%8,%9}, {%0,%1,%2,%3};"
    : "+f"(c[0]), "+f"(c[1]), "+f"(c[2]), "+f"(c[3])
    : "r"(a[0]), "r"(a[1]), "r"(a[2]), "r"(a[3]), "r"(b0), "r"(b1));
}

// stage 128 Q rows with 384 threads (3072 x 16B)
__device__ __forceinline__ void stage_q(char* sdst, const __nv_bfloat16* gsrc, int tid){
  const char* gb = (const char*)gsrc;
  #pragma unroll
  for (int i = 0; i < 8; i++){
    int idx = tid + i*ATH;
    int r = idx / 24, o = idx % 24;
    cpa16(sdst + r*SROW_B + o*16, gb + (size_t)r*384 + o*16);
  }
}
// stage 32 key rows with this group's 128 threads (768 x 16B)
__device__ __forceinline__ void stage_k(char* sdst, const __nv_bfloat16* gsrc, int gtid){
  const char* gb = (const char*)gsrc;
  #pragma unroll
  for (int i = 0; i < 6; i++){
    int idx = gtid + i*128;
    int r = idx / 24, o = idx % 24;
    cpa16(sdst + r*SROW_B + o*16, gb + (size_t)r*384 + o*16);
  }
}

__global__ void __launch_bounds__(ATH,1) attn_kernel(float* __restrict__ out){
  extern __shared__ char sm_c[];
  char* sm = sm_c;
  float* rsum = (float*)(sm + SRS_OFF);
  float* invp = (float*)(sm + SINV_OFF);

  const int tid = threadIdx.x;
  const int lane = tid & 31, wid = tid >> 5;
  const int gidx = wid >> 2;        // warp-group 0/1/2 (chunk residue class)
  const int gtid = tid & 127;
  const int wr = wid & 3;           // row-warp within group
  const int g = lane >> 2, t = lane & 3;
  const int barid = 1 + gidx;
  const int b = blockIdx.y, rb = blockIdx.x;

  const int NJg = (130 - gidx) / 3;  // 43,43,42 chunks per pass
  const int NJ2 = 2*NJg;

  const uint32_t smem_base = (uint32_t)__cvta_generic_to_shared(sm);

  const uint32_t aoff0 = (uint32_t)((wr*32 +  0 + (lane & 15))*SROW_B + ((lane >> 4) & 1)*16);
  const uint32_t aoff1 = (uint32_t)((wr*32 + 16 + (lane & 15))*SROW_B + ((lane >> 4) & 1)*16);
  const uint32_t boff = (uint32_t)(((lane & 7) + ((lane >> 1) & 8))*SROW_B + (lane & 8)*2);

  const __nv_bfloat16* Qg = g_Q + ((size_t)b*NL + (size_t)rb*128)*NKE;
  const __nv_bfloat16* Kg = g_K + (size_t)b*NL*NKE;

  stage_q(sm + SQ_OFF, Qg, tid);
  stage_k(sm + SKB(gidx,0), Kg + (size_t)(gidx)*CHUNK*NKE, gtid);
  cpcommit();
  stage_k(sm + SKB(gidx,1), Kg + (size_t)(gidx+3)*CHUNK*NKE, gtid);
  cpcommit();
  cpwait1();
  __syncthreads();

  uint32_t afr[12][2][4];
  {
    const uint32_t aA0 = smem_base + SQ_OFF + aoff0;
    const uint32_t aA1 = smem_base + SQ_OFF + aoff1;
    #pragma unroll
    for (int ks = 0; ks < 12; ks++){
      ldsm4(afr[ks][0], aA0 + ks*32);
      ldsm4(afr[ks][1], aA1 + ks*32);
    }
  }

  float esum[2][2] = {{0.f,0.f},{0.f,0.f}};
  float vinv[2][2] = {{0.f,0.f},{0.f,0.f}};

  for (int j = 0; j < NJ2; j++){
    if (j > 0){
      cpwait1();
      groupbar(barid);
    }
    {
      int nx = j + 2;
      if (nx < NJ2){
        int cg = gidx + 3*(nx >= NJg ? nx - NJg : nx);
        stage_k(sm + SKB(gidx, nx % 3), Kg + (size_t)cg*CHUNK*NKE, gtid);
      }
      cpcommit();
    }

    const uint32_t bB = smem_base + SKB(gidx, j % 3) + boff;

    float acc[2][4][4];
    #pragma unroll
    for (int mt=0;mt<2;mt++)
      #pragma unroll
      for (int nt=0;nt<4;nt++)
        #pragma unroll
        for (int i=0;i<4;i++) acc[mt][nt][i]=0.f;

    #pragma unroll
    for (int ks = 0; ks < 12; ks++){
      uint32_t br0[4], br1[4];
      ldsm4(br0, bB + ks*32);
      ldsm4(br1, bB + 16*SROW_B + ks*32);
      mma16816(acc[0][0], afr[ks][0], br0[0], br0[1]);
      mma16816(acc[1][0], afr[ks][1], br0[0], br0[1]);
      mma16816(acc[0][1], afr[ks][0], br0[2], br0[3]);
      mma16816(acc[1][1], afr[ks][1], br0[2], br0[3]);
      mma16816(acc[0][2], afr[ks][0], br1[0], br1[1]);
      mma16816(acc[1][2], afr[ks][1], br1[0], br1[1]);
      mma16816(acc[0][3], afr[ks][0], br1[2], br1[3]);
      mma16816(acc[1][3], afr[ks][1], br1[2], br1[3]);
    }

    if (j < NJg){
      #pragma unroll
      for (int mt=0;mt<2;mt++)
        #pragma unroll
        for (int nt=0;nt<4;nt++){
          esum[mt][0] += fexp2(acc[mt][nt][0]*SCALE_LOG2E) + fexp2(acc[mt][nt][1]*SCALE_LOG2E);
          esum[mt][1] += fexp2(acc[mt][nt][2]*SCALE_LOG2E) + fexp2(acc[mt][nt][3]*SCALE_LOG2E);
        }
    } else {
      int cg = gidx + 3*(j - NJg);
      #pragma unroll
      for (int mt=0;mt<2;mt++){
        int r0 = rb*128 + wr*32 + mt*16 + g;
        float* o0 = out + ((size_t)b*NL + r0)*NL + cg*CHUNK + t*2;
        float* o1 = o0 + (size_t)8*NL;
        #pragma unroll
        for (int nt=0;nt<4;nt++){
          float w00 = fexp2(acc[mt][nt][0]*SCALE_LOG2E)*vinv[mt][0];
          float w01 = fexp2(acc[mt][nt][1]*SCALE_LOG2E)*vinv[mt][0];
          float w10 = fexp2(acc[mt][nt][2]*SCALE_LOG2E)*vinv[mt][1];
          float w11 = fexp2(acc[mt][nt][3]*SCALE_LOG2E)*vinv[mt][1];
          float2 v0 = make_float2(w00 > THRESH ? w00 : 0.f, w01 > THRESH ? w01 : 0.f);
          float2 v1 = make_float2(w10 > THRESH ? w10 : 0.f, w11 > THRESH ? w11 : 0.f);
          *(float2*)(o0 + nt*8) = v0;
          *(float2*)(o1 + nt*8) = v1;
        }
      }
    }

    if (j == NJg-1){
      #pragma unroll
      for (int mt=0;mt<2;mt++)
        #pragma unroll
        for (int hh=0;hh<2;hh++){
          float v = esum[mt][hh];
          v += __shfl_xor_sync(0xffffffffu, v, 1);
          v += __shfl_xor_sync(0xffffffffu, v, 2);
          esum[mt][hh] = v;
        }
      if (t == 0){
        #pragma unroll
        for (int mt=0;mt<2;mt++){
          rsum[gidx*128 + wr*32 + mt*16 + g]     = esum[mt][0];
          rsum[gidx*128 + wr*32 + mt*16 + g + 8] = esum[mt][1];
        }
      }
      __syncthreads();
      if (tid < 128) invp[tid] = 1.0f / (rsum[tid] + rsum[128 + tid] + rsum[256 + tid]);
      __syncthreads();
      #pragma unroll
      for (int mt=0;mt<2;mt++){
        vinv[mt][0] = invp[wr*32 + mt*16 + g];
        vinv[mt][1] = invp[wr*32 + mt*16 + g + 8];
      }
    }
  }
}

// ---------------- launch ----------------
extern "C" void kernel_launch(void* const* d_in, const int* in_sizes, int n_in,
                              void* d_out, int out_size){
  const float* q  = (const float*)d_in[0];
  const float* k  = (const float*)d_in[1];
  const float* W1 = (const float*)d_in[2];
  const float* W2 = (const float*)d_in[3];
  float* out = (float*)d_out;

  cudaFuncSetAttribute(proj_kernel, cudaFuncAttributeMaxDynamicSharedMemorySize, SA_BYTES);
  cudaFuncSetAttribute(attn_kernel, cudaFuncAttributeMaxDynamicSharedMemorySize, SB_TOTAL);

  proj_kernel<<<2*NB*NL/(PJ_POS*PJ_GROUPS), 256, SA_BYTES>>>(q, k, W1, W2);
  attn_kernel<<<dim3(NL/128, NB), ATH, SB_TOTAL>>>(out);
}

// round 17
// speedup vs baseline: 1.1112x; 1.0206x over previous
#include <cuda_runtime.h>
#include <cuda_bf16.h>
#include <cstdint>
#include <cstddef>

#define NB   4
#define NC   64
#define NL   4096
#define NH   128
#define NKE  192          // [hi|x|x] split-bf16 extended K dimension

#define SCALE_LOG2E 14.4269504088896340737f   // 10 * log2(e)
#define THRESH 1e-3f

typedef unsigned long long ull;

// ---------------- device scratch (no allocations allowed) ----------------
__device__ __align__(256) __nv_bfloat16 g_Q[NB*NL*NKE];   // [b][l][192] = [qhi|qlo|qhi]
__device__ __align__(256) __nv_bfloat16 g_K[NB*NL*NKE];   // [b][l][192] = [khi|khi|klo]

// ---------------- packed f32x2 helpers ----------------
#define FMA_F32X2(d, a, b, c) \
  asm("fma.rn.f32x2 %0, %1, %2, %3;" : "=l"(d) : "l"(a), "l"(b), "l"(c))
#define PACK_F32X2(out, lo, hi) \
  asm("mov.b64 %0, {%1, %2};" : "=l"(out) : "f"(lo), "f"(hi))
#define UNPACK_F32X2(lo, hi, in) \
  asm("mov.b64 {%0, %1}, %2;" : "=f"(lo), "=f"(hi) : "l"(in))

__device__ __forceinline__ void cpa16(void* sptr, const void* gptr){
  uint32_t s = (uint32_t)__cvta_generic_to_shared(sptr);
  asm volatile("cp.async.cg.shared.global [%0], [%1], 16;" :: "r"(s), "l"(gptr));
}
__device__ __forceinline__ void cpcommit(){ asm volatile("cp.async.commit_group;"); }
__device__ __forceinline__ void cpwait0(){ asm volatile("cp.async.wait_group 0;"); }
__device__ __forceinline__ void cpwait1(){ asm volatile("cp.async.wait_group 1;"); }

// ---------------- projection: f32x2 FMA + cp.async double-buffered x ----------------
#define PJ_POS 32
#define PJ_GROUPS 4
#define W1T_PITCH 132   // [c][j]
#define W2_PITCH 132    // [o][j]
#define XS2_PITCH 40    // [c][p], 160B rows (16B aligned)
#define HS2_PITCH 36    // [j][p]
#define SA_W1T 0
#define SA_W2  (NC*W1T_PITCH)                    // 8448
#define SA_XS  (SA_W2 + NC*W2_PITCH)             // 16896
#define SA_HS2 (SA_XS + 2*NC*XS2_PITCH)          // 22016
#define SA_FLOATS (SA_HS2 + NH*HS2_PITCH)        // 26624
#define SA_BYTES (SA_FLOATS*4)                   // 106496

__global__ void __launch_bounds__(256,2) proj_kernel(const float* __restrict__ xq,
                                                     const float* __restrict__ xk,
                                                     const float* __restrict__ W1,
                                                     const float* __restrict__ W2){
  extern __shared__ float sm_f[];
  float* sm = sm_f;
  const int tid = threadIdx.x;
  const int bpt = NL / (PJ_POS*PJ_GROUPS);     // 32 blocks per (tensor,batch)
  const int tb  = blockIdx.x / bpt;            // 0..7  (0..3 = query, 4..7 = key)
  const int base = (blockIdx.x % bpt) * (PJ_POS*PJ_GROUPS);
  const bool isQ = (tb < NB);
  const int b   = tb & 3;
  const float* __restrict__ src = isQ ? xq : xk;
  __nv_bfloat16* __restrict__ dst = isQ ? g_Q : g_K;

  // prologue: async-stage xs for group 0
  {
    const char* gsrc = (const char*)(src + (size_t)b*NC*NL + base);
    for (int idx = tid; idx < NC*8; idx += 256){
      int c = idx >> 3, ch = idx & 7;
      cpa16((char*)sm + (SA_XS + c*XS2_PITCH + ch*4)*4, gsrc + (size_t)c*NL*4 + ch*16);
    }
    cpcommit();
  }
  // weights staged ONCE per CTA (overlaps with xs0 cp.async)
  for (int i = tid; i < NH*NC; i += 256){
    int j = i >> 6, c = i & 63;
    sm[SA_W1T + c*W1T_PITCH + j] = W1[i];      // W1t[c][j]
  }
  for (int i = tid; i < NC*NH; i += 256){
    int o = i >> 7, j = i & 127;
    sm[SA_W2 + o*W2_PITCH + j] = W2[i];        // W2[o][j]
  }

  const int lanegrp = tid & 31;
  const int pg      = tid >> 5;

  for (int grp = 0; grp < PJ_GROUPS; grp++){
    cpwait0();         // xs[grp] arrived (only one group in flight at a time)
    __syncthreads();   // W ready (first iter) / all warps done with xs[grp-1] buffer

    // prefetch xs[grp+1] into the other buffer; lands during this group's compute
    if (grp + 1 < PJ_GROUPS){
      const int nl0 = base + (grp+1)*PJ_POS;
      const float* xsb = sm + SA_XS + ((grp+1) & 1)*NC*XS2_PITCH;
      const char* gsrc = (const char*)(src + (size_t)b*NC*NL + nl0);
      for (int idx = tid; idx < NC*8; idx += 256){
        int c = idx >> 3, ch = idx & 7;
        cpa16((char*)(xsb + c*XS2_PITCH + ch*4), gsrc + (size_t)c*NL*4 + ch*16);
      }
    }
    cpcommit();

    const int l0 = base + grp*PJ_POS;
    const float* xs = sm + SA_XS + (grp & 1)*NC*XS2_PITCH;

    // ---- phase 1: h = leakyrelu(W1 @ x) ----
    // lane owns 4 consecutive j = lanegrp*4..+3; warp owns positions pg*4..+3
    {
      ull accp[2][4];   // [jpair][pi]
      #pragma unroll
      for (int jp=0;jp<2;jp++)
        #pragma unroll
        for (int pi=0;pi<4;pi++) accp[jp][pi] = 0ull;

      #pragma unroll 4
      for (int c = 0; c < NC; c++){
        const float4 wv = *(const float4*)&sm[SA_W1T + c*W1T_PITCH + lanegrp*4];
        const float4 xv = *(const float4*)&xs[c*XS2_PITCH + pg*4];   // broadcast: 4 positions
        ull w01 = ((const ull*)&wv)[0];
        ull w23 = ((const ull*)&wv)[1];
        #pragma unroll
        for (int pi=0;pi<4;pi++){
          float xsv = (pi==0) ? xv.x : (pi==1) ? xv.y : (pi==2) ? xv.z : xv.w;
          ull s; PACK_F32X2(s, xsv, xsv);
          FMA_F32X2(accp[0][pi], w01, s, accp[0][pi]);
          FMA_F32X2(accp[1][pi], w23, s, accp[1][pi]);
        }
      }
      // unpack + leakyrelu + store hs[j][p]
      #pragma unroll
      for (int jp=0;jp<2;jp++){
        float hv0[4], hv1[4];
        #pragma unroll
        for (int pi=0;pi<4;pi++){
          float lo, hi;
          UNPACK_F32X2(lo, hi, accp[jp][pi]);
          lo = lo >= 0.f ? lo : 0.01f*lo;
          hi = hi >= 0.f ? hi : 0.01f*hi;
          hv0[pi] = lo; hv1[pi] = hi;
        }
        int j0 = lanegrp*4 + jp*2;
        *(float4*)&sm[SA_HS2 + j0*HS2_PITCH + pg*4]     = make_float4(hv0[0],hv0[1],hv0[2],hv0[3]);
        *(float4*)&sm[SA_HS2 + (j0+1)*HS2_PITCH + pg*4] = make_float4(hv1[0],hv1[1],hv1[2],hv1[3]);
      }
    }
    __syncwarp();   // h columns for warp pg are warp-private

    // ---- phase 2: y = W2 @ h ; normalize ; split to bf16 ----
    {
      ull acc2p[2][2];   // [oi][pp]
      acc2p[0][0]=0ull; acc2p[0][1]=0ull; acc2p[1][0]=0ull; acc2p[1][1]=0ull;

      #pragma unroll 4
      for (int j4 = 0; j4 < NH; j4 += 4){
        const float4 w0 = *(const float4*)&sm[SA_W2 + lanegrp*W2_PITCH + j4];
        const float4 w1 = *(const float4*)&sm[SA_W2 + (lanegrp+32)*W2_PITCH + j4];
        #pragma unroll
        for (int jj=0;jj<4;jj++){
          int j = j4 + jj;
          ull h01 = *(const ull*)&sm[SA_HS2 + j*HS2_PITCH + pg*4];
          ull h23 = *(const ull*)&sm[SA_HS2 + j*HS2_PITCH + pg*4 + 2];
          float w0j = (jj==0) ? w0.x : (jj==1) ? w0.y : (jj==2) ? w0.z : w0.w;
          float w1j = (jj==0) ? w1.x : (jj==1) ? w1.y : (jj==2) ? w1.z : w1.w;
          ull s0, s1;
          PACK_F32X2(s0, w0j, w0j);
          PACK_F32X2(s1, w1j, w1j);
          FMA_F32X2(acc2p[0][0], s0, h01, acc2p[0][0]);
          FMA_F32X2(acc2p[0][1], s0, h23, acc2p[0][1]);
          FMA_F32X2(acc2p[1][0], s1, h01, acc2p[1][0]);
          FMA_F32X2(acc2p[1][1], s1, h23, acc2p[1][1]);
        }
      }
      float acc[2][4];
      #pragma unroll
      for (int oi=0;oi<2;oi++)
        #pragma unroll
        for (int pp=0;pp<2;pp++){
          float lo, hi;
          UNPACK_F32X2(lo, hi, acc2p[oi][pp]);
          acc[oi][2*pp]   = lo;
          acc[oi][2*pp+1] = hi;
        }
      #pragma unroll
      for (int pi=0;pi<4;pi++){
        float ssq = acc[0][pi]*acc[0][pi] + acc[1][pi]*acc[1][pi];
        #pragma unroll
        for (int off=16; off; off>>=1) ssq += __shfl_xor_sync(0xffffffffu, ssq, off);
        float inv = 1.0f / fmaxf(sqrtf(ssq), 1e-12f);
        int p = pg*4 + pi;
        size_t rowbase = ((size_t)b*NL + l0 + p) * NKE;
        #pragma unroll
        for (int oi=0;oi<2;oi++){
          int o = lanegrp + oi*32;
          float v = acc[oi][pi] * inv;
          __nv_bfloat16 hi = __float2bfloat16(v);
          __nv_bfloat16 lo = __float2bfloat16(v - __bfloat162float(hi));
          if (isQ){
            dst[rowbase + o]       = hi;
            dst[rowbase + 64 + o]  = lo;
            dst[rowbase + 128 + o] = hi;
          } else {
            dst[rowbase + o]       = hi;
            dst[rowbase + 64 + o]  = hi;
            dst[rowbase + 128 + o] = lo;
          }
        }
      }
    }
  }
}

// ----- attention: THREE independent warp-groups pipelined over chunk residues -----
#define ATH   384            // 12 warps: 3 groups x 4 row-warps
#define CHUNK 32             // key-cols per chunk
#define SROW_B 400           // padded smem row stride (192*2=384 data + 16 pad)
#define QTILE_B (128*SROW_B)           // 51200
#define KTILE_B (CHUNK*SROW_B)         // 12800
#define SQ_OFF  0
#define SKB(gr,s) (QTILE_B + ((gr)*3+(s))*KTILE_B)
#define SRS_OFF (QTILE_B + 9*KTILE_B)  // 166400: float rsum[3][128]
#define SINV_OFF (SRS_OFF + 1536)
#define SB_TOTAL (SINV_OFF + 512)      // 168448 B

__device__ __forceinline__ float fexp2(float x){
  float y;
  asm("ex2.approx.ftz.f32 %0, %1;" : "=f"(y) : "f"(x));
  return y;
}
__device__ __forceinline__ void groupbar(int id){
  asm volatile("bar.sync %0, 128;" :: "r"(id) : "memory");
}

// stage 128 Q rows with 384 threads (3072 x 16B)
__device__ __forceinline__ void stage_q(char* sdst, const __nv_bfloat16* gsrc, int tid){
  const char* gb = (const char*)gsrc;
  #pragma unroll
  for (int i = 0; i < 8; i++){
    int idx = tid + i*ATH;
    int r = idx / 24, o = idx % 24;
    cpa16(sdst + r*SROW_B + o*16, gb + (size_t)r*384 + o*16);
  }
}
// stage 32 key rows with this group's 128 threads (768 x 16B)
__device__ __forceinline__ void stage_k(char* sdst, const __nv_bfloat16* gsrc, int gtid){
  const char* gb = (const char*)gsrc;
  #pragma unroll
  for (int i = 0; i < 6; i++){
    int idx = gtid + i*128;
    int r = idx / 24, o = idx % 24;
    cpa16(sdst + r*SROW_B + o*16, gb + (size_t)r*384 + o*16);
  }
}

__device__ __forceinline__ void ldsm4(uint32_t (&r)[4], uint32_t saddr){
  asm volatile("ldmatrix.sync.aligned.m8n8.x4.shared.b16 {%0,%1,%2,%3}, [%4];"
    : "=r"(r[0]), "=r"(r[1]), "=r"(r[2]), "=r"(r[3]) : "r"(saddr));
}
__device__ __forceinline__ void mma16816(float (&c)[4], const uint32_t (&a)[4],
                                         uint32_t b0, uint32_t b1){
  asm volatile(
    "mma.sync.aligned.m16n8k16.row.col.f32.bf16.bf16.f32 "
    "{%0,%1,%2,%3}, {%4,%5,%6,%7}, {%8,%9}, {%0,%1,%2,%3};"
    : "+f"(c[0]), "+f"(c[1]), "+f"(c[2]), "+f"(c[3])
    : "r"(a[0]), "r"(a[1]), "r"(a[2]), "r"(a[3]), "r"(b0), "r"(b1));
}

__global__ void __launch_bounds__(ATH,1) attn_kernel(float* __restrict__ out){
  extern __shared__ char sm_c[];
  char* sm = sm_c;
  float* rsum = (float*)(sm + SRS_OFF);
  float* invp = (float*)(sm + SINV_OFF);

  const int tid = threadIdx.x;
  const int lane = tid & 31, wid = tid >> 5;
  const int gidx = wid >> 2;        // warp-group 0/1/2 (chunk residue class)
  const int gtid = tid & 127;
  const int wr = wid & 3;           // row-warp within group
  const int g = lane >> 2, t = lane & 3;
  const int barid = 1 + gidx;
  const int b = blockIdx.y, rb = blockIdx.x;

  const int NJg = (130 - gidx) / 3;  // 43,43,42 chunks per pass
  const int NJ2 = 2*NJg;

  const uint32_t smem_base = (uint32_t)__cvta_generic_to_shared(sm);

  const uint32_t aoff0 = (uint32_t)((wr*32 +  0 + (lane & 15))*SROW_B + ((lane >> 4) & 1)*16);
  const uint32_t aoff1 = (uint32_t)((wr*32 + 16 + (lane & 15))*SROW_B + ((lane >> 4) & 1)*16);
  const uint32_t boff = (uint32_t)(((lane & 7) + ((lane >> 1) & 8))*SROW_B + (lane & 8)*2);

  const __nv_bfloat16* Qg = g_Q + ((size_t)b*NL + (size_t)rb*128)*NKE;
  const __nv_bfloat16* Kg = g_K + (size_t)b*NL*NKE;

  stage_q(sm + SQ_OFF, Qg, tid);
  stage_k(sm + SKB(gidx,0), Kg + (size_t)(gidx)*CHUNK*NKE, gtid);
  cpcommit();
  stage_k(sm + SKB(gidx,1), Kg + (size_t)(gidx+3)*CHUNK*NKE, gtid);
  cpcommit();
  cpwait1();
  __syncthreads();

  uint32_t afr[12][2][4];
  {
    const uint32_t aA0 = smem_base + SQ_OFF + aoff0;
    const uint32_t aA1 = smem_base + SQ_OFF + aoff1;
    #pragma unroll
    for (int ks = 0; ks < 12; ks++){
      ldsm4(afr[ks][0], aA0 + ks*32);
      ldsm4(afr[ks][1], aA1 + ks*32);
    }
  }

  float esum[2][2] = {{0.f,0.f},{0.f,0.f}};
  float vinv[2][2] = {{0.f,0.f},{0.f,0.f}};

  for (int j = 0; j < NJ2; j++){
    if (j > 0){
      cpwait1();
      groupbar(barid);
    }
    {
      int nx = j + 2;
      if (nx < NJ2){
        int cg = gidx + 3*(nx >= NJg ? nx - NJg : nx);
        stage_k(sm + SKB(gidx, nx % 3), Kg + (size_t)cg*CHUNK*NKE, gtid);
      }
      cpcommit();
    }

    const uint32_t bB = smem_base + SKB(gidx, j % 3) + boff;

    float acc[2][4][4];
    #pragma unroll
    for (int mt=0;mt<2;mt++)
      #pragma unroll
      for (int nt=0;nt<4;nt++)
        #pragma unroll
        for (int i=0;i<4;i++) acc[mt][nt][i]=0.f;

    #pragma unroll
    for (int ks = 0; ks < 12; ks++){
      uint32_t br0[4], br1[4];
      ldsm4(br0, bB + ks*32);
      ldsm4(br1, bB + 16*SROW_B + ks*32);
      mma16816(acc[0][0], afr[ks][0], br0[0], br0[1]);
      mma16816(acc[1][0], afr[ks][1], br0[0], br0[1]);
      mma16816(acc[0][1], afr[ks][0], br0[2], br0[3]);
      mma16816(acc[1][1], afr[ks][1], br0[2], br0[3]);
      mma16816(acc[0][2], afr[ks][0], br1[0], br1[1]);
      mma16816(acc[1][2], afr[ks][1], br1[0], br1[1]);
      mma16816(acc[0][3], afr[ks][0], br1[2], br1[3]);
      mma16816(acc[1][3], afr[ks][1], br1[2], br1[3]);
    }

    if (j < NJg){
      #pragma unroll
      for (int mt=0;mt<2;mt++)
        #pragma unroll
        for (int nt=0;nt<4;nt++){
          esum[mt][0] += fexp2(acc[mt][nt][0]*SCALE_LOG2E) + fexp2(acc[mt][nt][1]*SCALE_LOG2E);
          esum[mt][1] += fexp2(acc[mt][nt][2]*SCALE_LOG2E) + fexp2(acc[mt][nt][3]*SCALE_LOG2E);
        }
    } else {
      int cg = gidx + 3*(j - NJg);
      #pragma unroll
      for (int mt=0;mt<2;mt++){
        int r0 = rb*128 + wr*32 + mt*16 + g;
        float* o0 = out + ((size_t)b*NL + r0)*NL + cg*CHUNK + t*2;
        float* o1 = o0 + (size_t)8*NL;
        #pragma unroll
        for (int nt=0;nt<4;nt++){
          float w00 = fexp2(acc[mt][nt][0]*SCALE_LOG2E)*vinv[mt][0];
          float w01 = fexp2(acc[mt][nt][1]*SCALE_LOG2E)*vinv[mt][0];
          float w10 = fexp2(acc[mt][nt][2]*SCALE_LOG2E)*vinv[mt][1];
          float w11 = fexp2(acc[mt][nt][3]*SCALE_LOG2E)*vinv[mt][1];
          float2 v0 = make_float2(w00 > THRESH ? w00 : 0.f, w01 > THRESH ? w01 : 0.f);
          float2 v1 = make_float2(w10 > THRESH ? w10 : 0.f, w11 > THRESH ? w11 : 0.f);
          *(float2*)(o0 + nt*8) = v0;
          *(float2*)(o1 + nt*8) = v1;
        }
      }
    }

    if (j == NJg-1){
      #pragma unroll
      for (int mt=0;mt<2;mt++)
        #pragma unroll
        for (int hh=0;hh<2;hh++){
          float v = esum[mt][hh];
          v += __shfl_xor_sync(0xffffffffu, v, 1);
          v += __shfl_xor_sync(0xffffffffu, v, 2);
          esum[mt][hh] = v;
        }
      if (t == 0){
        #pragma unroll
        for (int mt=0;mt<2;mt++){
          rsum[gidx*128 + wr*32 + mt*16 + g]     = esum[mt][0];
          rsum[gidx*128 + wr*32 + mt*16 + g + 8] = esum[mt][1];
        }
      }
      __syncthreads();
      if (tid < 128) invp[tid] = 1.0f / (rsum[tid] + rsum[128 + tid] + rsum[256 + tid]);
      __syncthreads();
      #pragma unroll
      for (int mt=0;mt<2;mt++){
        vinv[mt][0] = invp[wr*32 + mt*16 + g];
        vinv[mt][1] = invp[wr*32 + mt*16 + g + 8];
      }
    }
  }
}

// ---------------- launch ----------------
extern "C" void kernel_launch(void* const* d_in, const int* in_sizes, int n_in,
                              void* d_out, int out_size){
  const float* q  = (const float*)d_in[0];
  const float* k  = (const float*)d_in[1];
  const float* W1 = (const float*)d_in[2];
  const float* W2 = (const float*)d_in[3];
  float* out = (float*)d_out;

  cudaFuncSetAttribute(proj_kernel, cudaFuncAttributeMaxDynamicSharedMemorySize, SA_BYTES);
  cudaFuncSetAttribute(attn_kernel, cudaFuncAttributeMaxDynamicSharedMemorySize, SB_TOTAL);

  proj_kernel<<<2*NB*NL/(PJ_POS*PJ_GROUPS), 256, SA_BYTES>>>(q, k, W1, W2);
  attn_kernel<<<dim3(NL/128, NB), ATH, SB_TOTAL>>>(out);
}